// round 4
// baseline (speedup 1.0000x reference)
#include <cuda_runtime.h>

// preds: [16,8,17,128,128] f32  -> flattened N=128, K=17, H=W=128
// gt:    [16,8,10,17,2]   f32  -> N=128, P=10, K=17, (x,y)
// out:   2 floats: total_within, total_across

#define N_FLAT 128
#define P_NUM 10
#define K_NUM 17
#define HW 128
#define PK (P_NUM * K_NUM)   // 170
#define FP_SCALE 1099511627776.0f   // 2^40 fixed-point scale

__device__ unsigned long long g_acc_w = 0ull;
__device__ unsigned long long g_acc_a = 0ull;
__device__ unsigned int g_count = 0u;

__global__ __launch_bounds__(192) void group_loss_fused(
    const float* __restrict__ preds,
    const float* __restrict__ gt,
    float* __restrict__ out)
{
    const int n = blockIdx.x;
    const int t = threadIdx.x;

    __shared__ float s_val[PK];   // masked gathered value (0 if invalid)
    __shared__ float s_msk[PK];   // validity 0/1

    if (t < PK) {
        const int p = t / K_NUM;
        const int k = t - p * K_NUM;
        const float2 g = ((const float2*)gt)[(n * P_NUM + p) * K_NUM + k];
        // jnp.round = round half to even; rintf matches (default RN mode)
        const int x = (int)rintf(g.x * 0.25f);
        const int y = (int)rintf(g.y * 0.25f);
        const bool valid = (x >= 0) & (x < HW) & (y >= 0) & (y < HW);
        const int xc = min(max(x, 0), HW - 1);
        const int yc = min(max(y, 0), HW - 1);
        const float v = preds[((n * K_NUM + k) * HW + yc) * HW + xc];
        s_val[t] = valid ? v : 0.0f;
        s_msk[t] = valid ? 1.0f : 0.0f;
    }
    __syncthreads();

    if (t >= 32) return;            // warps 1..5 done; warp 0 finishes alone
    const int lane = t;

    // per-person one-pass moments (lanes >= P_NUM stay zero)
    float sum = 0.0f, sumsq = 0.0f, cnt = 0.0f;
    if (lane < P_NUM) {
        #pragma unroll
        for (int k = 0; k < K_NUM; k++) {
            const float v = s_val[lane * K_NUM + k];   // already masked
            sum   += v;
            sumsq += v * v;
            cnt   += s_msk[lane * K_NUM + k];
        }
    }
    const float safe = fmaxf(cnt, 1.0f);
    const float e = sum / safe;
    // E[(v-e)^2] = E[v^2] - e^2 over valid kps (m in {0,1} => v_masked^2 = v^2 m)
    float within_p = (cnt > 0.0f) ? fmaxf(sumsq / safe - e * e, 0.0f) : 0.0f;
    const float pv = (cnt > 0.0f) ? 1.0f : 0.0f;

    // broadcast all person embeds / validity into registers of every lane
    float ej[P_NUM], pj[P_NUM];
    #pragma unroll
    for (int j = 0; j < P_NUM; j++) {
        ej[j] = __shfl_sync(0xffffffffu, e,  j);
        pj[j] = __shfl_sync(0xffffffffu, pv, j);
    }

    // pairwise hinge: lane i computes its row (full 10x10 minus diagonal)
    float hinge_row = 0.0f, denom_row = 0.0f;
    if (lane < P_NUM) {
        #pragma unroll
        for (int j = 0; j < P_NUM; j++) {
            const float w = (j == lane) ? 0.0f : pv * pj[j];
            hinge_row += w * fmaxf(1.0f - fabsf(ej[j] - e), 0.0f);
            denom_row += w;
        }
    }

    // butterfly reduce three values over the warp (lanes >= 10 carry zeros)
    #pragma unroll
    for (int off = 16; off > 0; off >>= 1) {
        within_p  += __shfl_xor_sync(0xffffffffu, within_p,  off);
        hinge_row += __shfl_xor_sync(0xffffffffu, hinge_row, off);
        denom_row += __shfl_xor_sync(0xffffffffu, denom_row, off);
    }

    if (lane == 0) {
        const float within = within_p * (1.0f / (float)P_NUM);
        const float across = (denom_row > 0.0f) ? hinge_row / denom_row : 0.0f;

        // deterministic order-invariant accumulation: 2^-40 fixed point, u64 atomics
        atomicAdd(&g_acc_w, (unsigned long long)(long long)llrintf(within * FP_SCALE));
        atomicAdd(&g_acc_a, (unsigned long long)(long long)llrintf(across * FP_SCALE));
        __threadfence();
        const unsigned int prev = atomicAdd(&g_count, 1u);
        if (prev == (unsigned int)(N_FLAT - 1)) {
            // all 128 contributions are at L2 (fenced before their counter adds)
            const unsigned long long w = atomicAdd(&g_acc_w, 0ull);
            const unsigned long long a = atomicAdd(&g_acc_a, 0ull);
            out[0] = (float)((double)(long long)w * (1.0 / ((double)FP_SCALE * N_FLAT)));
            out[1] = (float)((double)(long long)a * (1.0 / ((double)FP_SCALE * N_FLAT)));
            // reset for next graph replay (kernel boundary orders these)
            g_acc_w = 0ull;
            g_acc_a = 0ull;
            g_count = 0u;
        }
    }
}

extern "C" void kernel_launch(void* const* d_in, const int* in_sizes, int n_in,
                              void* d_out, int out_size)
{
    const float* preds = (const float*)d_in[0];
    const float* gt    = (const float*)d_in[1];
    float* out = (float*)d_out;
    group_loss_fused<<<N_FLAT, 192>>>(preds, gt, out);
}